// round 8
// baseline (speedup 1.0000x reference)
#include <cuda_runtime.h>
#include <cuda_bf16.h>
#include <math_constants.h>
#include <cstdint>

#define NROWS 16384
#define KCODES 8192
#define DIM 256
#define CAP 64
#define NTILES 64          // 8192 / 128 codes per tile
#define PADB 528           // smem row pitch bytes (256 bf16 = 512 + 16 pad)
#define ZSZ (128 * PADB)   // 67584 per tile buffer
#define SMEM_TOT (3 * ZSZ + 1024)

// ---------------- static device scratch ----------------
__device__ __align__(16) __nv_bfloat16 g_eb[KCODES * DIM];
__device__ int    g_cand[NROWS * CAP];
__device__ int    g_cnt[NROWS];
__device__ unsigned char g_over[NROWS];
__device__ float  g_e2[KCODES];
__device__ int    g_e2max_bits;
__device__ double g_part[NROWS];

// ---------------- base-target PTX helpers ----------------
__device__ __forceinline__ uint32_t smem_u32(const void* p) {
    uint32_t a;
    asm("{ .reg .u64 t; cvta.to.shared.u64 t, %1; cvt.u32.u64 %0, t; }" : "=r"(a) : "l"(p));
    return a;
}
#define CPA16(dst, src) \
    asm volatile("cp.async.cg.shared.global [%0], [%1], 16;" :: "r"(dst), "l"(src))
#define CPA_COMMIT() asm volatile("cp.async.commit_group;" ::: "memory")
#define CPA_WAIT1()  asm volatile("cp.async.wait_group 1;" ::: "memory")
#define CPA_WAIT0()  asm volatile("cp.async.wait_group 0;" ::: "memory")
#define LDSM4(r, addr) \
    asm volatile("ldmatrix.sync.aligned.m8n8.x4.shared.b16 {%0,%1,%2,%3}, [%4];" \
                 : "=r"((r)[0]), "=r"((r)[1]), "=r"((r)[2]), "=r"((r)[3]) : "r"(addr))

__device__ __forceinline__ void mma16816(float* c, const uint32_t* a, uint32_t b0, uint32_t b1) {
    asm volatile(
        "mma.sync.aligned.m16n8k16.row.col.f32.bf16.bf16.f32 "
        "{%0,%1,%2,%3},{%4,%5,%6,%7},{%8,%9},{%0,%1,%2,%3};"
        : "+f"(c[0]), "+f"(c[1]), "+f"(c[2]), "+f"(c[3])
        : "r"(a[0]), "r"(a[1]), "r"(a[2]), "r"(a[3]), "r"(b0), "r"(b1));
}

// ---------------- aux kernels ----------------
// Convert emb to bf16 only (z converted in-kernel now); init e2max.
__global__ void conv_kernel(const float* __restrict__ e) {
    if (blockIdx.x == 0 && threadIdx.x == 0) g_e2max_bits = 0;
    size_t v4 = (size_t)blockIdx.x * 256 + threadIdx.x;
    float4 f = ((const float4*)e)[v4];
    __nv_bfloat162* d = (__nv_bfloat162*)g_eb + v4 * 2;
    d[0] = __floats2bfloat162_rn(f.x, f.y);
    d[1] = __floats2bfloat162_rn(f.z, f.w);
}

__global__ void e2_kernel(const float* __restrict__ emb) {
    int k = blockIdx.x * 8 + (threadIdx.x >> 5);
    int lane = threadIdx.x & 31;
    const float* p = emb + (size_t)k * DIM;
    float s = 0.f;
#pragma unroll
    for (int i = 0; i < 8; i++) { float v = p[lane + 32 * i]; s = __fmaf_rn(v, v, s); }
#pragma unroll
    for (int o = 16; o; o >>= 1) s += __shfl_down_sync(0xffffffffu, s, o);
    if (lane == 0) { g_e2[k] = s; atomicMax(&g_e2max_bits, __float_as_int(s)); }
}

// ---------------- phase 1: mma.sync bf16 GEMM + dot-margin pruning ----------
// 512 threads = 16 warps: warp = (rowgroup 0..7, nhalf 0..1).
__global__ __launch_bounds__(512, 1) void vq_mma(const float* __restrict__ z_e) {
    extern __shared__ char sm[];
    int*   scnt = (int*)(sm + 3 * ZSZ);
    float* x2s  = (float*)(sm + 3 * ZSZ + 512);
    const uint32_t sb = smem_u32(sm);
    const int tid = threadIdx.x, lane = tid & 31, w = tid >> 5;
    const int rg = w & 7, nh = w >> 3;
    const int n0 = blockIdx.x * 128;

    if (tid < 128) scnt[tid] = 0;

    // prefetch emb tile 0 (cp.async group 0)
    {
        const char* ge = (const char*)g_eb;
#pragma unroll
        for (int t = 0; t < 8; t++) {
            int i = tid + t * 512;
            int row = i >> 5, q = i & 31;
            CPA16(sb + ZSZ + row * PADB + q * 16, ge + row * 512 + q * 16);
        }
        CPA_COMMIT();
    }

    // z tile: load fp32, convert to bf16, store padded (overlaps emb prefetch)
    {
        const float4* gz = (const float4*)(z_e + (size_t)n0 * DIM);
#pragma unroll
        for (int t = 0; t < 16; t++) {
            int i = tid + t * 512;              // 8192 float4 total
            int row = i >> 6, q = i & 63;
            float4 f = gz[row * 64 + q];
            __nv_bfloat162 h0 = __floats2bfloat162_rn(f.x, f.y);
            __nv_bfloat162 h1 = __floats2bfloat162_rn(f.z, f.w);
            uint2 u;
            u.x = *(uint32_t*)&h0; u.y = *(uint32_t*)&h1;
            *(uint2*)(sm + row * PADB + q * 8) = u;
        }
    }
    __syncthreads();

    // x2 per row from bf16 tile (margin use only; constant inflated to cover)
    if (tid < 128) {
        const __nv_bfloat162* zr = (const __nv_bfloat162*)(sm + tid * PADB);
        float s = 0.f;
#pragma unroll 8
        for (int d = 0; d < 128; d++) {
            float2 f = __bfloat1622float2(zr[d]);
            s = __fmaf_rn(f.x, f.x, s);
            s = __fmaf_rn(f.y, f.y, s);
        }
        x2s[tid] = s;
    }
    __syncthreads();

    // pruning state: rows (rg*16 + g) and (+8), g = lane>>2
    const int lm = lane >> 3, lr = lane & 7;
    const int g = lane >> 2, tq = lane & 3;
    const int rowloc0 = rg * 16 + g;
    const float e2max = __int_as_float(g_e2max_bits);
    float margd[2], rmax[2], thr[2];
#pragma unroll
    for (int rs = 0; rs < 2; rs++) {
        margd[rs] = 0.0079f * sqrtf(x2s[rowloc0 + rs * 8] * e2max) + 1.0e-4f;
        rmax[rs] = -CUDART_INF_F;
        thr[rs]  = -CUDART_INF_F;
    }
    const uint32_t aAddr = sb + (uint32_t)(rg * 16 + lr + (lm & 1) * 8) * PADB + ((lm >> 1) << 4);
    const uint32_t boff  = (uint32_t)(lr + ((lm >> 1) & 1) * 8) * PADB + ((lm & 1) << 4);

    for (int t = 0; t < NTILES; t++) {
        if (t < NTILES - 1) {   // prefetch next emb tile into other buffer
            const char* ge = (const char*)(g_eb + (size_t)(t + 1) * 128 * DIM);
            uint32_t db = sb + ZSZ + ((t + 1) & 1) * ZSZ;
#pragma unroll
            for (int u = 0; u < 8; u++) {
                int i = tid + u * 512;
                int row = i >> 5, q = i & 31;
                CPA16(db + row * PADB + q * 16, ge + row * 512 + q * 16);
            }
            CPA_COMMIT();
            CPA_WAIT1();
        } else {
            CPA_WAIT0();
        }
        __syncthreads();

        const uint32_t bB = sb + ZSZ + (t & 1) * ZSZ + boff;
#pragma unroll 1
        for (int q = 0; q < 2; q++) {             // this warp's 2 n-quads
            const int nq = nh * 2 + q;
            float C[4][4];
#pragma unroll
            for (int i = 0; i < 4; i++)
#pragma unroll
                for (int j = 0; j < 4; j++) C[i][j] = 0.f;

            uint32_t addr0 = bB + (uint32_t)(nq * 32) * PADB;
            uint32_t addr1 = addr0 + 16 * PADB;
#pragma unroll
            for (int ks = 0; ks < 16; ks++) {
                uint32_t a[4], b0[4], b1[4];
                LDSM4(a,  aAddr + ks * 32);
                LDSM4(b0, addr0 + ks * 32);
                LDSM4(b1, addr1 + ks * 32);
                mma16816(C[0], a, b0[0], b0[1]);
                mma16816(C[1], a, b0[2], b0[3]);
                mma16816(C[2], a, b1[0], b1[1]);
                mma16816(C[3], a, b1[2], b1[3]);
            }
            // epilogue: capture k iff dot >= rowmax - margd (superset of true argmin)
            int kc = t * 128 + nq * 32 + 2 * tq;
#pragma unroll
            for (int nt = 0; nt < 4; nt++) {
#pragma unroll
                for (int r = 0; r < 4; r++) {
                    float d = C[nt][r];
                    int rs = r >> 1;
                    if (d >= thr[rs]) {
                        int rl = rowloc0 + rs * 8;
                        int idx = atomicAdd(&scnt[rl], 1);
                        if (idx < CAP)
                            g_cand[(size_t)(n0 + rl) * CAP + idx] = kc + nt * 8 + (r & 1);
                        if (d > rmax[rs]) { rmax[rs] = d; thr[rs] = d - margd[rs]; }
                    }
                }
            }
            // share running max across the 4 owner lanes every 32 codes
#pragma unroll
            for (int rs = 0; rs < 2; rs++) {
                float m = rmax[rs];
                m = fmaxf(m, __shfl_xor_sync(0xffffffffu, m, 1));
                m = fmaxf(m, __shfl_xor_sync(0xffffffffu, m, 2));
                rmax[rs] = m;
                thr[rs] = m - margd[rs];
            }
        }
        __syncthreads();
    }

    if (tid < 128) {
        int c = scnt[tid];
        g_cnt[n0 + tid] = c < CAP ? c : CAP;
        g_over[n0 + tid] = (c > CAP) ? 1 : 0;
    }
}

// ---------------- phase 2: exact fp32 rescoring + fused gather/writeback ----
__global__ void vq_exact(const float* __restrict__ z_e, const float* __restrict__ emb,
                         float* __restrict__ out) {
    __shared__ float zrow[8][DIM];
    int wid = threadIdx.x >> 5, lane = threadIdx.x & 31;
    int row = blockIdx.x * 8 + wid;
    {
        const float4* gz = (const float4*)(z_e + (size_t)row * DIM);
#pragma unroll
        for (int i = 0; i < 2; i++) {
            float4 v = gz[lane + 32 * i];
            *(float4*)&zrow[wid][4 * (lane + 32 * i)] = v;
        }
    }
    __syncwarp();
    const float* zr = zrow[wid];
    float x2 = 0.f;
    for (int d = 0; d < DIM; d++) x2 = __fmaf_rn(zr[d], zr[d], x2);

    float bt = CUDART_INF_F;
    int bk = 0x7fffffff;
    int cnt = g_cnt[row];
    bool over = g_over[row] != 0;
    int total = over ? KCODES : cnt;
    for (int c = lane; c < total; c += 32) {
        int k = over ? c : g_cand[(size_t)row * CAP + c];
        const float4* er = (const float4*)(emb + (size_t)k * DIM);
        float dot = 0.f;
#pragma unroll 8
        for (int q = 0; q < DIM / 4; q++) {
            float4 e4 = er[q];
            dot = __fmaf_rn(zr[4 * q + 0], e4.x, dot);
            dot = __fmaf_rn(zr[4 * q + 1], e4.y, dot);
            dot = __fmaf_rn(zr[4 * q + 2], e4.z, dot);
            dot = __fmaf_rn(zr[4 * q + 3], e4.w, dot);
        }
        float S = __fadd_rn(x2, g_e2[k]);
        float tt = __fadd_rn(S, -2.0f * dot);
        if (tt < bt || (tt == bt && k < bk)) { bt = tt; bk = k; }
    }
#pragma unroll
    for (int o = 16; o; o >>= 1) {
        float to = __shfl_down_sync(0xffffffffu, bt, o);
        int ko = __shfl_down_sync(0xffffffffu, bk, o);
        if (to < bt || (to == bt && ko < bk)) { bt = to; bk = ko; }
    }
    bk = __shfl_sync(0xffffffffu, bk, 0);

    // fused gather: z_q_st + loss partial + code output
    const float4* er = (const float4*)(emb + (size_t)bk * DIM);
    float4* po = (float4*)(out + (size_t)row * DIM);
    float sq = 0.f;
#pragma unroll
    for (int j = 0; j < 2; j++) {
        int q = lane + 32 * j;
        float4 e4 = er[q];
        const float* zp = &zrow[wid][4 * q];
        float4 o4;
        float d0 = __fsub_rn(e4.x, zp[0]); o4.x = __fadd_rn(zp[0], d0); sq = __fmaf_rn(d0, d0, sq);
        float d1 = __fsub_rn(e4.y, zp[1]); o4.y = __fadd_rn(zp[1], d1); sq = __fmaf_rn(d1, d1, sq);
        float d2 = __fsub_rn(e4.z, zp[2]); o4.z = __fadd_rn(zp[2], d2); sq = __fmaf_rn(d2, d2, sq);
        float d3 = __fsub_rn(e4.w, zp[3]); o4.w = __fadd_rn(zp[3], d3); sq = __fmaf_rn(d3, d3, sq);
        po[q] = o4;
    }
#pragma unroll
    for (int o = 16; o; o >>= 1) sq += __shfl_down_sync(0xffffffffu, sq, o);
    if (lane == 0) {
        g_part[row] = (double)sq;
        out[(size_t)NROWS * DIM + 1 + row] = (float)bk;
    }
}

__global__ void vq_loss(float* __restrict__ out) {
    __shared__ double sd[1024];
    int tid = threadIdx.x;
    double s = 0.0;
    for (int i = tid; i < NROWS; i += 1024) s += g_part[i];
    sd[tid] = s;
    __syncthreads();
    for (int st = 512; st; st >>= 1) {
        if (tid < st) sd[tid] += sd[tid + st];
        __syncthreads();
    }
    if (tid == 0) {
        float m = (float)(sd[0] / (double)((size_t)NROWS * DIM));
        out[(size_t)NROWS * DIM] = __fadd_rn(m, 0.25f * m);
    }
}

// ---------------------------------------------------------------------------
extern "C" void kernel_launch(void* const* d_in, const int* in_sizes, int n_in,
                              void* d_out, int out_size) {
    const float* z_e = (const float*)d_in[0];
    const float* emb = (const float*)d_in[1];
    if (n_in >= 2 && in_sizes[0] == KCODES * DIM && in_sizes[1] == NROWS * DIM) {
        const float* t = z_e; z_e = emb; emb = t;
    }
    float* out = (float*)d_out;

    cudaFuncSetAttribute(vq_mma, cudaFuncAttributeMaxDynamicSharedMemorySize, SMEM_TOT);

    conv_kernel<<<KCODES * DIM / 4 / 256, 256>>>(emb);
    e2_kernel<<<KCODES / 8, 256>>>(emb);
    vq_mma<<<NROWS / 128, 512, SMEM_TOT>>>(z_e);
    vq_exact<<<NROWS / 8, 256>>>(z_e, emb, out);
    vq_loss<<<1, 1024>>>(out);
}

// round 10
// speedup vs baseline: 5.1136x; 5.1136x over previous
#include <cuda_runtime.h>
#include <cuda_bf16.h>
#include <math_constants.h>
#include <cstdint>

#define NROWS 16384
#define KCODES 8192
#define DIM 256
#define CAP 64
#define NTILES 64          // 8192 / 128 codes per tile
#define PADB 528           // smem row pitch bytes (256 bf16 = 512 + 16 pad)
#define ZSZ (128 * PADB)   // 67584 per tile buffer
#define SMEM_TOT (3 * ZSZ + 1024)

// ---------------- static device scratch ----------------
__device__ __align__(16) __nv_bfloat16 g_eb[KCODES * DIM];
__device__ int    g_cand[NROWS * CAP];
__device__ int    g_cnt[NROWS];
__device__ unsigned char g_over[NROWS];
__device__ float  g_e2[KCODES];
__device__ int    g_e2max_bits;
__device__ double g_part[NROWS];

// ---------------- base-target PTX helpers ----------------
__device__ __forceinline__ uint32_t smem_u32(const void* p) {
    uint32_t a;
    asm("{ .reg .u64 t; cvta.to.shared.u64 t, %1; cvt.u32.u64 %0, t; }" : "=r"(a) : "l"(p));
    return a;
}
#define CPA16(dst, src) \
    asm volatile("cp.async.cg.shared.global [%0], [%1], 16;" :: "r"(dst), "l"(src))
#define CPA_COMMIT() asm volatile("cp.async.commit_group;" ::: "memory")
#define CPA_WAIT1()  asm volatile("cp.async.wait_group 1;" ::: "memory")
#define CPA_WAIT0()  asm volatile("cp.async.wait_group 0;" ::: "memory")
#define LDSM4(r, addr) \
    asm volatile("ldmatrix.sync.aligned.m8n8.x4.shared.b16 {%0,%1,%2,%3}, [%4];" \
                 : "=r"((r)[0]), "=r"((r)[1]), "=r"((r)[2]), "=r"((r)[3]) : "r"(addr))

__device__ __forceinline__ void mma16816(float* c, const uint32_t* a, uint32_t b0, uint32_t b1) {
    asm volatile(
        "mma.sync.aligned.m16n8k16.row.col.f32.bf16.bf16.f32 "
        "{%0,%1,%2,%3},{%4,%5,%6,%7},{%8,%9},{%0,%1,%2,%3};"
        : "+f"(c[0]), "+f"(c[1]), "+f"(c[2]), "+f"(c[3])
        : "r"(a[0]), "r"(a[1]), "r"(a[2]), "r"(a[3]), "r"(b0), "r"(b1));
}

// ---------------- aux kernels ----------------
__global__ void conv_kernel(const float* __restrict__ e) {
    if (blockIdx.x == 0 && threadIdx.x == 0) g_e2max_bits = 0;
    size_t v4 = (size_t)blockIdx.x * 256 + threadIdx.x;
    float4 f = ((const float4*)e)[v4];
    __nv_bfloat162* d = (__nv_bfloat162*)g_eb + v4 * 2;
    d[0] = __floats2bfloat162_rn(f.x, f.y);
    d[1] = __floats2bfloat162_rn(f.z, f.w);
}

__global__ void e2_kernel(const float* __restrict__ emb) {
    int k = blockIdx.x * 8 + (threadIdx.x >> 5);
    int lane = threadIdx.x & 31;
    const float* p = emb + (size_t)k * DIM;
    float s = 0.f;
#pragma unroll
    for (int i = 0; i < 8; i++) { float v = p[lane + 32 * i]; s = __fmaf_rn(v, v, s); }
#pragma unroll
    for (int o = 16; o; o >>= 1) s += __shfl_down_sync(0xffffffffu, s, o);
    if (lane == 0) { g_e2[k] = s; atomicMax(&g_e2max_bits, __float_as_int(s)); }
}

// ---------------- phase 1: mma.sync bf16 GEMM + dot-margin pruning ----------
// 256 threads, 8 warps; warp w owns rows w*16..w*16+15; persistent A fragments.
__global__ __launch_bounds__(256, 1) void vq_mma(const float* __restrict__ z_e) {
    extern __shared__ char sm[];
    int*   scnt = (int*)(sm + 3 * ZSZ);
    float* x2s  = (float*)(sm + 3 * ZSZ + 512);
    const uint32_t sb = smem_u32(sm);
    const int tid = threadIdx.x, lane = tid & 31, w = tid >> 5;
    const int n0 = blockIdx.x * 128;

    if (tid < 128) scnt[tid] = 0;

    // prefetch emb tile 0 (cp.async group 0)
    {
        const char* ge = (const char*)g_eb;
#pragma unroll
        for (int t = 0; t < 16; t++) {
            int i = tid + t * 256;
            int row = i >> 5, q = i & 31;
            CPA16(sb + ZSZ + row * PADB + q * 16, ge + row * 512 + q * 16);
        }
        CPA_COMMIT();
    }

    // z tile: load fp32, convert to bf16, store padded (overlaps emb prefetch)
    {
        const float4* gz = (const float4*)(z_e + (size_t)n0 * DIM);
#pragma unroll
        for (int t = 0; t < 32; t++) {
            int i = tid + t * 256;              // 8192 float4 total
            int row = i >> 6, q = i & 63;
            float4 f = gz[row * 64 + q];
            __nv_bfloat162 h0 = __floats2bfloat162_rn(f.x, f.y);
            __nv_bfloat162 h1 = __floats2bfloat162_rn(f.z, f.w);
            uint2 u;
            u.x = *(uint32_t*)&h0; u.y = *(uint32_t*)&h1;
            *(uint2*)(sm + row * PADB + q * 8) = u;
        }
    }
    __syncthreads();

    // x2 per row from bf16 tile (margin use only; constant inflated to cover)
    if (tid < 128) {
        const __nv_bfloat162* zr = (const __nv_bfloat162*)(sm + tid * PADB);
        float s = 0.f;
#pragma unroll 8
        for (int d = 0; d < 128; d++) {
            float2 f = __bfloat1622float2(zr[d]);
            s = __fmaf_rn(f.x, f.x, s);
            s = __fmaf_rn(f.y, f.y, s);
        }
        x2s[tid] = s;
    }
    __syncthreads();

    // persistent A fragments: this warp's 16 rows x full D=256
    const int lm = lane >> 3, lr = lane & 7;
    uint32_t a[16][4];
    {
        uint32_t aAddr = sb + (uint32_t)(w * 16 + lr + (lm & 1) * 8) * PADB + ((lm >> 1) << 4);
#pragma unroll
        for (int ks = 0; ks < 16; ks++) LDSM4(a[ks], aAddr + ks * 32);
    }

    // pruning state: rows (w*16 + g) and (+8), g = lane>>2
    const int g = lane >> 2, tq = lane & 3;
    const int rowloc0 = w * 16 + g;
    const float e2max = __int_as_float(g_e2max_bits);
    float margd[2], rmax[2], thr[2];
#pragma unroll
    for (int rs = 0; rs < 2; rs++) {
        margd[rs] = 0.0079f * sqrtf(x2s[rowloc0 + rs * 8] * e2max) + 1.0e-4f;
        rmax[rs] = -CUDART_INF_F;
        thr[rs]  = -CUDART_INF_F;
    }
    const uint32_t boff = (uint32_t)(lr + ((lm >> 1) & 1) * 8) * PADB + ((lm & 1) << 4);

    for (int t = 0; t < NTILES; t++) {
        if (t < NTILES - 1) {   // prefetch next emb tile into other buffer
            const char* ge = (const char*)(g_eb + (size_t)(t + 1) * 128 * DIM);
            uint32_t db = sb + ZSZ + ((t + 1) & 1) * ZSZ;
#pragma unroll
            for (int u = 0; u < 16; u++) {
                int i = tid + u * 256;
                int row = i >> 5, q = i & 31;
                CPA16(db + row * PADB + q * 16, ge + row * 512 + q * 16);
            }
            CPA_COMMIT();
            CPA_WAIT1();
        } else {
            CPA_WAIT0();
        }
        __syncthreads();

        const uint32_t bB = sb + ZSZ + (t & 1) * ZSZ + boff;
#pragma unroll 1
        for (int nqp = 0; nqp < 2; nqp++) {       // pair of n-quads = 64 codes
            float C[8][4];
#pragma unroll
            for (int i = 0; i < 8; i++)
#pragma unroll
                for (int j = 0; j < 4; j++) C[i][j] = 0.f;

            // B addresses: quad q in {0,1}: base + (nqp*64 + q*32)*PADB (+16*PADB)
            uint32_t ba[4];
            ba[0] = bB + (uint32_t)(nqp * 64) * PADB;
            ba[1] = ba[0] + 16 * PADB;
            ba[2] = ba[0] + 32 * PADB;
            ba[3] = ba[2] + 16 * PADB;

            // software-pipelined B: ping-pong register buffers
            uint32_t b[2][16];
#pragma unroll
            for (int p = 0; p < 4; p++) LDSM4(&b[0][p * 4], ba[p]);
#pragma unroll
            for (int ks = 0; ks < 16; ks++) {
                const int cur = ks & 1, nxt = cur ^ 1;
                if (ks < 15) {
#pragma unroll
                    for (int p = 0; p < 4; p++) LDSM4(&b[nxt][p * 4], ba[p] + (ks + 1) * 32);
                }
#pragma unroll
                for (int q = 0; q < 2; q++) {
                    mma16816(C[q * 4 + 0], a[ks], b[cur][q * 8 + 0], b[cur][q * 8 + 1]);
                    mma16816(C[q * 4 + 1], a[ks], b[cur][q * 8 + 2], b[cur][q * 8 + 3]);
                    mma16816(C[q * 4 + 2], a[ks], b[cur][q * 8 + 4], b[cur][q * 8 + 5]);
                    mma16816(C[q * 4 + 3], a[ks], b[cur][q * 8 + 6], b[cur][q * 8 + 7]);
                }
            }

            // epilogue: capture k iff dot >= rowmax - margd (superset of true argmin)
#pragma unroll
            for (int q = 0; q < 2; q++) {
                int kc = t * 128 + (nqp * 2 + q) * 32 + 2 * tq;
#pragma unroll
                for (int nt = 0; nt < 4; nt++) {
#pragma unroll
                    for (int r = 0; r < 4; r++) {
                        float d = C[q * 4 + nt][r];
                        int rs = r >> 1;
                        if (d >= thr[rs]) {
                            int rl = rowloc0 + rs * 8;
                            int idx = atomicAdd(&scnt[rl], 1);
                            if (idx < CAP)
                                g_cand[(size_t)(n0 + rl) * CAP + idx] = kc + nt * 8 + (r & 1);
                            if (d > rmax[rs]) { rmax[rs] = d; thr[rs] = d - margd[rs]; }
                        }
                    }
                }
            }
            // share running max across the 4 owner lanes every 64 codes
#pragma unroll
            for (int rs = 0; rs < 2; rs++) {
                float m = rmax[rs];
                m = fmaxf(m, __shfl_xor_sync(0xffffffffu, m, 1));
                m = fmaxf(m, __shfl_xor_sync(0xffffffffu, m, 2));
                rmax[rs] = m;
                thr[rs] = m - margd[rs];
            }
        }
        __syncthreads();
    }

    if (tid < 128) {
        int c = scnt[tid];
        g_cnt[n0 + tid] = c < CAP ? c : CAP;
        g_over[n0 + tid] = (c > CAP) ? 1 : 0;
    }
}

// ---------------- phase 2: exact fp32 rescoring + fused gather/writeback ----
__global__ void vq_exact(const float* __restrict__ z_e, const float* __restrict__ emb,
                         float* __restrict__ out) {
    __shared__ float zrow[8][DIM];
    int wid = threadIdx.x >> 5, lane = threadIdx.x & 31;
    int row = blockIdx.x * 8 + wid;
    {
        const float4* gz = (const float4*)(z_e + (size_t)row * DIM);
#pragma unroll
        for (int i = 0; i < 2; i++) {
            float4 v = gz[lane + 32 * i];
            *(float4*)&zrow[wid][4 * (lane + 32 * i)] = v;
        }
    }
    __syncwarp();
    const float* zr = zrow[wid];
    float x2 = 0.f;
    for (int d = 0; d < DIM; d++) x2 = __fmaf_rn(zr[d], zr[d], x2);

    float bt = CUDART_INF_F;
    int bk = 0x7fffffff;
    int cnt = g_cnt[row];
    bool over = g_over[row] != 0;
    int total = over ? KCODES : cnt;
    for (int c = lane; c < total; c += 32) {
        int k = over ? c : g_cand[(size_t)row * CAP + c];
        const float4* er = (const float4*)(emb + (size_t)k * DIM);
        float dot = 0.f;
#pragma unroll 8
        for (int q = 0; q < DIM / 4; q++) {
            float4 e4 = er[q];
            dot = __fmaf_rn(zr[4 * q + 0], e4.x, dot);
            dot = __fmaf_rn(zr[4 * q + 1], e4.y, dot);
            dot = __fmaf_rn(zr[4 * q + 2], e4.z, dot);
            dot = __fmaf_rn(zr[4 * q + 3], e4.w, dot);
        }
        float S = __fadd_rn(x2, g_e2[k]);
        float tt = __fadd_rn(S, -2.0f * dot);
        if (tt < bt || (tt == bt && k < bk)) { bt = tt; bk = k; }
    }
#pragma unroll
    for (int o = 16; o; o >>= 1) {
        float to = __shfl_down_sync(0xffffffffu, bt, o);
        int ko = __shfl_down_sync(0xffffffffu, bk, o);
        if (to < bt || (to == bt && ko < bk)) { bt = to; bk = ko; }
    }
    bk = __shfl_sync(0xffffffffu, bk, 0);

    // fused gather: z_q_st + loss partial + code output
    const float4* er = (const float4*)(emb + (size_t)bk * DIM);
    float4* po = (float4*)(out + (size_t)row * DIM);
    float sq = 0.f;
#pragma unroll
    for (int j = 0; j < 2; j++) {
        int q = lane + 32 * j;
        float4 e4 = er[q];
        const float* zp = &zrow[wid][4 * q];
        float4 o4;
        float d0 = __fsub_rn(e4.x, zp[0]); o4.x = __fadd_rn(zp[0], d0); sq = __fmaf_rn(d0, d0, sq);
        float d1 = __fsub_rn(e4.y, zp[1]); o4.y = __fadd_rn(zp[1], d1); sq = __fmaf_rn(d1, d1, sq);
        float d2 = __fsub_rn(e4.z, zp[2]); o4.z = __fadd_rn(zp[2], d2); sq = __fmaf_rn(d2, d2, sq);
        float d3 = __fsub_rn(e4.w, zp[3]); o4.w = __fadd_rn(zp[3], d3); sq = __fmaf_rn(d3, d3, sq);
        po[q] = o4;
    }
#pragma unroll
    for (int o = 16; o; o >>= 1) sq += __shfl_down_sync(0xffffffffu, sq, o);
    if (lane == 0) {
        g_part[row] = (double)sq;
        out[(size_t)NROWS * DIM + 1 + row] = (float)bk;
    }
}

__global__ void vq_loss(float* __restrict__ out) {
    __shared__ double sd[1024];
    int tid = threadIdx.x;
    double s = 0.0;
    for (int i = tid; i < NROWS; i += 1024) s += g_part[i];
    sd[tid] = s;
    __syncthreads();
    for (int st = 512; st; st >>= 1) {
        if (tid < st) sd[tid] += sd[tid + st];
        __syncthreads();
    }
    if (tid == 0) {
        float m = (float)(sd[0] / (double)((size_t)NROWS * DIM));
        out[(size_t)NROWS * DIM] = __fadd_rn(m, 0.25f * m);
    }
}

// ---------------------------------------------------------------------------
extern "C" void kernel_launch(void* const* d_in, const int* in_sizes, int n_in,
                              void* d_out, int out_size) {
    const float* z_e = (const float*)d_in[0];
    const float* emb = (const float*)d_in[1];
    if (n_in >= 2 && in_sizes[0] == KCODES * DIM && in_sizes[1] == NROWS * DIM) {
        const float* t = z_e; z_e = emb; emb = t;
    }
    float* out = (float*)d_out;

    cudaFuncSetAttribute(vq_mma, cudaFuncAttributeMaxDynamicSharedMemorySize, SMEM_TOT);

    conv_kernel<<<KCODES * DIM / 4 / 256, 256>>>(emb);
    e2_kernel<<<KCODES / 8, 256>>>(emb);
    vq_mma<<<NROWS / 128, 256, SMEM_TOT>>>(z_e);
    vq_exact<<<NROWS / 8, 256>>>(z_e, emb, out);
    vq_loss<<<1, 1024>>>(out);
}

// round 11
// speedup vs baseline: 6.9022x; 1.3498x over previous
#include <cuda_runtime.h>
#include <cuda_bf16.h>
#include <math_constants.h>
#include <cstdint>

#define NROWS 16384
#define KCODES 8192
#define DIM 256
#define CAP 64
#define NTILES 64          // 8192 / 128 codes per tile
#define ZB 65536           // one 128x256-bf16 tile, unpadded (512 B rows)
#define SMEM_TOT (3 * ZB + 2048)
// smem: [0,ZB) z tile | [ZB,2ZB) emb buf0 | [2ZB,3ZB) emb buf1 |
//       [3ZB,+512) scnt | [+512,+1024) x2s | [+1024,+1040) mbarriers

// ---------------- static device scratch ----------------
__device__ __align__(16) __nv_bfloat16 g_eb[KCODES * DIM];  // swizzled layout
__device__ int    g_cand[NROWS * CAP];
__device__ float  g_cdot[NROWS * CAP];
__device__ int    g_cnt[NROWS];
__device__ unsigned char g_over[NROWS];
__device__ float  g_thr[NROWS];
__device__ float  g_e2[KCODES];
__device__ int    g_e2max_bits;
__device__ double g_accum;

// ---------------- base-target PTX helpers ----------------
__device__ __forceinline__ uint32_t smem_u32(const void* p) {
    uint32_t a;
    asm("{ .reg .u64 t; cvta.to.shared.u64 t, %1; cvt.u32.u64 %0, t; }" : "=r"(a) : "l"(p));
    return a;
}
#define LDSM4(r, addr) \
    asm volatile("ldmatrix.sync.aligned.m8n8.x4.shared.b16 {%0,%1,%2,%3}, [%4];" \
                 : "=r"((r)[0]), "=r"((r)[1]), "=r"((r)[2]), "=r"((r)[3]) : "r"(addr))
#define MBARRIER_INIT(mb, c) \
    asm volatile("mbarrier.init.shared.b64 [%0], %1;" :: "r"((uint32_t)(mb)), "r"((uint32_t)(c)) : "memory")
#define MBARRIER_EXPECT_TX(mb, tx) \
    asm volatile("mbarrier.arrive.expect_tx.shared.b64 _, [%0], %1;" :: "r"((uint32_t)(mb)), "r"((uint32_t)(tx)) : "memory")
#define CPBULK(dst, src, bytes, mb) \
    asm volatile("cp.async.bulk.shared::cta.global.mbarrier::complete_tx::bytes [%0], [%1], %2, [%3];" \
                 :: "r"((uint32_t)(dst)), "l"(src), "r"((uint32_t)(bytes)), "r"((uint32_t)(mb)) : "memory")
#define MBARRIER_WAIT_PARITY(mb, par) do { \
    uint32_t _m = (uint32_t)(mb); uint32_t _p = (uint32_t)(par); uint32_t _d; \
    asm volatile("{\n\t.reg .pred p;\n\t" \
        "mbarrier.try_wait.parity.acquire.cta.shared::cta.b64 p, [%1], %2;\n\t" \
        "selp.b32 %0, 1, 0, p;\n\t}" : "=r"(_d) : "r"(_m), "r"(_p) : "memory"); \
    if (!_d) { \
        asm volatile("{\n\t.reg .pred P1;\n\tWL_%=:\n\t" \
            "mbarrier.try_wait.parity.acquire.cta.shared::cta.b64 P1, [%0], %1, 0x989680;\n\t" \
            "@P1 bra.uni WD_%=;\n\tbra.uni WL_%=;\n\tWD_%=:\n\t}" \
            :: "r"(_m), "r"(_p) : "memory"); \
    } } while (0)

__device__ __forceinline__ void mma16816(float* c, const uint32_t* a, uint32_t b0, uint32_t b1) {
    asm volatile(
        "mma.sync.aligned.m16n8k16.row.col.f32.bf16.bf16.f32 "
        "{%0,%1,%2,%3},{%4,%5,%6,%7},{%8,%9},{%0,%1,%2,%3};"
        : "+f"(c[0]), "+f"(c[1]), "+f"(c[2]), "+f"(c[3])
        : "r"(a[0]), "r"(a[1]), "r"(a[2]), "r"(a[3]), "r"(b0), "r"(b1));
}

// ---------------- aux kernels ----------------
// Convert emb to bf16 into XOR-swizzled layout: 16B chunk c of row r stored at c^(r&7).
__global__ void conv_kernel(const float* __restrict__ e) {
    if (blockIdx.x == 0 && threadIdx.x == 0) { g_e2max_bits = 0; g_accum = 0.0; }
    size_t v4 = (size_t)blockIdx.x * 256 + threadIdx.x;     // one float4 -> 8 bytes bf16
    float4 f = ((const float4*)e)[v4];
    int code = (int)(v4 >> 6), u8 = (int)(v4 & 63);
    int phys = (u8 >> 1) ^ (code & 7);
    char* dst = (char*)g_eb + (size_t)code * 512 + phys * 16 + (u8 & 1) * 8;
    __nv_bfloat162 h0 = __floats2bfloat162_rn(f.x, f.y);
    __nv_bfloat162 h1 = __floats2bfloat162_rn(f.z, f.w);
    uint2 u; u.x = *(uint32_t*)&h0; u.y = *(uint32_t*)&h1;
    *(uint2*)dst = u;
}

__global__ void e2_kernel(const float* __restrict__ emb) {
    int k = blockIdx.x * 8 + (threadIdx.x >> 5);
    int lane = threadIdx.x & 31;
    const float* p = emb + (size_t)k * DIM;
    float s = 0.f;
#pragma unroll
    for (int i = 0; i < 8; i++) { float v = p[lane + 32 * i]; s = __fmaf_rn(v, v, s); }
#pragma unroll
    for (int o = 16; o; o >>= 1) s += __shfl_down_sync(0xffffffffu, s, o);
    if (lane == 0) { g_e2[k] = s; atomicMax(&g_e2max_bits, __float_as_int(s)); }
}

// ---------------- phase 1: mma.sync bf16 GEMM + dot-margin pruning ----------
// 256 threads, 8 warps; warp w owns rows w*16..w*16+15; persistent A fragments.
// emb tiles streamed via cp.async.bulk (1 instr / 64KB), 2-deep mbarrier pipeline.
__global__ __launch_bounds__(256, 1) void vq_mma(const float* __restrict__ z_e) {
    extern __shared__ char sm[];
    int*   scnt = (int*)(sm + 3 * ZB);
    float* x2s  = (float*)(sm + 3 * ZB + 512);
    const uint32_t sb = smem_u32(sm);
    const uint32_t bar0 = sb + 3 * ZB + 1024, bar1 = bar0 + 8;
    const int tid = threadIdx.x, lane = tid & 31, w = tid >> 5;
    const int n0 = blockIdx.x * 128;

    if (tid < 128) scnt[tid] = 0;
    if (tid == 0) { MBARRIER_INIT(bar0, 1); MBARRIER_INIT(bar1, 1); }
    __syncthreads();
    if (tid == 0) {
        MBARRIER_EXPECT_TX(bar0, ZB);
        CPBULK(sb + ZB, (const char*)g_eb, ZB, bar0);
        MBARRIER_EXPECT_TX(bar1, ZB);
        CPBULK(sb + 2 * ZB, (const char*)g_eb + ZB, ZB, bar1);
    }

    // z tile: load fp32, convert to bf16, store swizzled (overlaps bulk loads)
    {
        const float4* gz = (const float4*)(z_e + (size_t)n0 * DIM);
#pragma unroll
        for (int t = 0; t < 32; t++) {
            int i = tid + t * 256;              // 8192 float4 total
            int row = i >> 6, u8 = i & 63;
            float4 f = gz[i];
            __nv_bfloat162 h0 = __floats2bfloat162_rn(f.x, f.y);
            __nv_bfloat162 h1 = __floats2bfloat162_rn(f.z, f.w);
            uint2 u; u.x = *(uint32_t*)&h0; u.y = *(uint32_t*)&h1;
            int phys = (u8 >> 1) ^ (row & 7);
            *(uint2*)(sm + row * 512 + phys * 16 + (u8 & 1) * 8) = u;
        }
    }
    __syncthreads();

    // x2 per row from bf16 tile (margin use only; permutation/order irrelevant)
    if (tid < 128) {
        const __nv_bfloat162* zr = (const __nv_bfloat162*)(sm + tid * 512);
        float s = 0.f;
#pragma unroll 8
        for (int d = 0; d < 128; d++) {
            float2 f = __bfloat1622float2(zr[d]);
            s = __fmaf_rn(f.x, f.x, s);
            s = __fmaf_rn(f.y, f.y, s);
        }
        x2s[tid] = s;
    }
    __syncthreads();

    // persistent A fragments: this warp's 16 rows x full D=256
    const int lm = lane >> 3, lr = lane & 7;
    const int ca = lm >> 1;                       // A k-halve select
    uint32_t a[16][4];
    {
        uint32_t aRow = sb + (uint32_t)(w * 16 + lr + (lm & 1) * 8) * 512;
#pragma unroll
        for (int ks = 0; ks < 16; ks++)
            LDSM4(a[ks], aRow + (uint32_t)(((2 * ks + ca) ^ lr) << 4));
    }

    // pruning state: rows (w*16 + g) and (+8), g = lane>>2
    const int g = lane >> 2, tq = lane & 3;
    const int rowloc0 = w * 16 + g;
    const float e2max = __int_as_float(g_e2max_bits);
    float margd[2], rmax[2], thr[2];
#pragma unroll
    for (int rs = 0; rs < 2; rs++) {
        margd[rs] = 0.0079f * sqrtf(x2s[rowloc0 + rs * 8] * e2max) + 1.0e-4f;
        rmax[rs] = -CUDART_INF_F;
        thr[rs]  = -CUDART_INF_F;
    }
    const int cb = lm & 1;                        // B k-halve select
    const uint32_t rB = (uint32_t)(((lm >> 1) & 1) * 8 + lr) * 512;

    for (int t = 0; t < NTILES; t++) {
        MBARRIER_WAIT_PARITY(t & 1 ? bar1 : bar0, (t >> 1) & 1);
        const uint32_t eB = sb + ZB + (uint32_t)(t & 1) * ZB;

#pragma unroll 1
        for (int nqp = 0; nqp < 2; nqp++) {       // pair of n-quads = 64 codes
            float C[8][4];
#pragma unroll
            for (int i = 0; i < 8; i++)
#pragma unroll
                for (int j = 0; j < 4; j++) C[i][j] = 0.f;

            uint32_t ba[4];
#pragma unroll
            for (int p = 0; p < 4; p++)
                ba[p] = eB + (uint32_t)(nqp * 64 + p * 16) * 512 + rB;

            uint32_t b[2][16];
#pragma unroll
            for (int p = 0; p < 4; p++)
                LDSM4(&b[0][p * 4], ba[p] + (uint32_t)((cb ^ lr) << 4));
#pragma unroll
            for (int ks = 0; ks < 16; ks++) {
                const int cur = ks & 1, nxt = cur ^ 1;
                if (ks < 15) {
                    uint32_t off = (uint32_t)(((2 * (ks + 1) + cb) ^ lr) << 4);
#pragma unroll
                    for (int p = 0; p < 4; p++) LDSM4(&b[nxt][p * 4], ba[p] + off);
                }
#pragma unroll
                for (int q = 0; q < 2; q++) {
                    mma16816(C[q * 4 + 0], a[ks], b[cur][q * 8 + 0], b[cur][q * 8 + 1]);
                    mma16816(C[q * 4 + 1], a[ks], b[cur][q * 8 + 2], b[cur][q * 8 + 3]);
                    mma16816(C[q * 4 + 2], a[ks], b[cur][q * 8 + 4], b[cur][q * 8 + 5]);
                    mma16816(C[q * 4 + 3], a[ks], b[cur][q * 8 + 6], b[cur][q * 8 + 7]);
                }
            }

            // epilogue: capture k (and its dot) iff dot >= rowmax - margd
#pragma unroll
            for (int q = 0; q < 2; q++) {
                int kc = t * 128 + (nqp * 2 + q) * 32 + 2 * tq;
#pragma unroll
                for (int nt = 0; nt < 4; nt++) {
#pragma unroll
                    for (int r = 0; r < 4; r++) {
                        float d = C[q * 4 + nt][r];
                        int rs = r >> 1;
                        if (d >= thr[rs]) {
                            int rl = rowloc0 + rs * 8;
                            int idx = atomicAdd(&scnt[rl], 1);
                            if (idx < CAP) {
                                g_cand[(size_t)(n0 + rl) * CAP + idx] = kc + nt * 8 + (r & 1);
                                g_cdot[(size_t)(n0 + rl) * CAP + idx] = d;
                            }
                            if (d > rmax[rs]) { rmax[rs] = d; thr[rs] = d - margd[rs]; }
                        }
                    }
                }
            }
            // share running max across the 4 owner lanes every 64 codes
#pragma unroll
            for (int rs = 0; rs < 2; rs++) {
                float m = rmax[rs];
                m = fmaxf(m, __shfl_xor_sync(0xffffffffu, m, 1));
                m = fmaxf(m, __shfl_xor_sync(0xffffffffu, m, 2));
                rmax[rs] = m;
                thr[rs] = m - margd[rs];
            }
        }
        __syncthreads();   // all warps done with buffer t&1
        if (tid == 0 && t + 2 < NTILES) {
            uint32_t mb = (t & 1) ? bar1 : bar0;
            MBARRIER_EXPECT_TX(mb, ZB);
            CPBULK(sb + ZB + (uint32_t)(t & 1) * ZB,
                   (const char*)g_eb + (size_t)(t + 2) * ZB, ZB, mb);
        }
    }

    // final thresholds + counts
    if (tq == 0) {
        g_thr[n0 + rowloc0]     = rmax[0] - margd[0];
        g_thr[n0 + rowloc0 + 8] = rmax[1] - margd[1];
    }
    __syncthreads();
    if (tid < 128) {
        int c = scnt[tid];
        g_cnt[n0 + tid] = c < CAP ? c : CAP;
        g_over[n0 + tid] = (c > CAP) ? 1 : 0;
    }
}

// ---------------- phase 2: exact fp32 rescoring (final-threshold filtered) --
__global__ void vq_exact(const float* __restrict__ z_e, const float* __restrict__ emb,
                         float* __restrict__ out) {
    __shared__ float zrow[8][DIM];
    int wid = threadIdx.x >> 5, lane = threadIdx.x & 31;
    int row = blockIdx.x * 8 + wid;
    {
        const float4* gz = (const float4*)(z_e + (size_t)row * DIM);
#pragma unroll
        for (int i = 0; i < 2; i++) {
            float4 v = gz[lane + 32 * i];
            *(float4*)&zrow[wid][4 * (lane + 32 * i)] = v;
        }
    }
    __syncwarp();
    const float* zr = zrow[wid];
    float x2 = 0.f;
    for (int d = 0; d < DIM; d++) x2 = __fmaf_rn(zr[d], zr[d], x2);

    float bt = CUDART_INF_F;
    int bk = 0x7fffffff;
    int cnt = g_cnt[row];
    bool over = g_over[row] != 0;
    float thrf = g_thr[row];
    int total = over ? KCODES : cnt;
    for (int c = lane; c < total; c += 32) {
        int k;
        if (over) k = c;
        else {
            if (g_cdot[(size_t)row * CAP + c] < thrf) continue;   // prefix junk
            k = g_cand[(size_t)row * CAP + c];
        }
        const float4* er = (const float4*)(emb + (size_t)k * DIM);
        float dot = 0.f;
#pragma unroll 8
        for (int q = 0; q < DIM / 4; q++) {
            float4 e4 = er[q];
            dot = __fmaf_rn(zr[4 * q + 0], e4.x, dot);
            dot = __fmaf_rn(zr[4 * q + 1], e4.y, dot);
            dot = __fmaf_rn(zr[4 * q + 2], e4.z, dot);
            dot = __fmaf_rn(zr[4 * q + 3], e4.w, dot);
        }
        float S = __fadd_rn(x2, g_e2[k]);
        float tt = __fadd_rn(S, -2.0f * dot);
        if (tt < bt || (tt == bt && k < bk)) { bt = tt; bk = k; }
    }
#pragma unroll
    for (int o = 16; o; o >>= 1) {
        float to = __shfl_down_sync(0xffffffffu, bt, o);
        int ko = __shfl_down_sync(0xffffffffu, bk, o);
        if (to < bt || (to == bt && ko < bk)) { bt = to; bk = ko; }
    }
    bk = __shfl_sync(0xffffffffu, bk, 0);

    // fused gather: z_q_st + loss partial + code output
    const float4* er = (const float4*)(emb + (size_t)bk * DIM);
    float4* po = (float4*)(out + (size_t)row * DIM);
    float sq = 0.f;
#pragma unroll
    for (int j = 0; j < 2; j++) {
        int q = lane + 32 * j;
        float4 e4 = er[q];
        const float* zp = &zrow[wid][4 * q];
        float4 o4;
        float d0 = __fsub_rn(e4.x, zp[0]); o4.x = __fadd_rn(zp[0], d0); sq = __fmaf_rn(d0, d0, sq);
        float d1 = __fsub_rn(e4.y, zp[1]); o4.y = __fadd_rn(zp[1], d1); sq = __fmaf_rn(d1, d1, sq);
        float d2 = __fsub_rn(e4.z, zp[2]); o4.z = __fadd_rn(zp[2], d2); sq = __fmaf_rn(d2, d2, sq);
        float d3 = __fsub_rn(e4.w, zp[3]); o4.w = __fadd_rn(zp[3], d3); sq = __fmaf_rn(d3, d3, sq);
        po[q] = o4;
    }
#pragma unroll
    for (int o = 16; o; o >>= 1) sq += __shfl_down_sync(0xffffffffu, sq, o);
    if (lane == 0) {
        atomicAdd(&g_accum, (double)sq);
        out[(size_t)NROWS * DIM + 1 + row] = (float)bk;
    }
}

__global__ void vq_loss(float* __restrict__ out) {
    float m = (float)(g_accum / (double)((size_t)NROWS * DIM));
    out[(size_t)NROWS * DIM] = __fadd_rn(m, 0.25f * m);
}

// ---------------------------------------------------------------------------
extern "C" void kernel_launch(void* const* d_in, const int* in_sizes, int n_in,
                              void* d_out, int out_size) {
    const float* z_e = (const float*)d_in[0];
    const float* emb = (const float*)d_in[1];
    if (n_in >= 2 && in_sizes[0] == KCODES * DIM && in_sizes[1] == NROWS * DIM) {
        const float* t = z_e; z_e = emb; emb = t;
    }
    float* out = (float*)d_out;

    cudaFuncSetAttribute(vq_mma, cudaFuncAttributeMaxDynamicSharedMemorySize, SMEM_TOT);

    conv_kernel<<<KCODES * DIM / 4 / 256, 256>>>(emb);
    e2_kernel<<<KCODES / 8, 256>>>(emb);
    vq_mma<<<NROWS / 128, 256, SMEM_TOT>>>(z_e);
    vq_exact<<<NROWS / 8, 256>>>(z_e, emb, out);
    vq_loss<<<1, 1>>>(out);
}

// round 13
// speedup vs baseline: 7.4359x; 1.0773x over previous
#include <cuda_runtime.h>
#include <cuda_bf16.h>
#include <math_constants.h>
#include <cstdint>

#define NROWS 16384
#define KCODES 8192
#define DIM 256
#define CAP 64
#define MT 64              // rows per CTA
#define TN 64              // codes per emb tile
#define NT2 128            // 8192 / 64 tiles
#define EB 32768           // one 64x256-bf16 tile, unpadded (512 B rows)
#define SMEM_TOT (3 * EB + 1024)
// smem: [0,EB) z tile | [EB,2EB) emb buf0 | [2EB,3EB) emb buf1 |
//       [3EB,+256) scnt | [+256,+512) x2s | [+512,+528) mbarriers

// ---------------- static device scratch ----------------
__device__ __align__(16) __nv_bfloat16 g_eb[KCODES * DIM];  // swizzled layout
__device__ int    g_cand[NROWS * CAP];
__device__ float  g_cdot[NROWS * CAP];
__device__ int    g_cnt[NROWS];
__device__ unsigned char g_over[NROWS];
__device__ float  g_thr[NROWS];
__device__ float  g_e2[KCODES];
__device__ int    g_e2max_bits;   // monotone across replays (same data -> same max)
__device__ double g_accum;

// ---------------- base-target PTX helpers ----------------
__device__ __forceinline__ uint32_t smem_u32(const void* p) {
    uint32_t a;
    asm("{ .reg .u64 t; cvta.to.shared.u64 t, %1; cvt.u32.u64 %0, t; }" : "=r"(a) : "l"(p));
    return a;
}
#define LDSM4(r, addr) \
    asm volatile("ldmatrix.sync.aligned.m8n8.x4.shared.b16 {%0,%1,%2,%3}, [%4];" \
                 : "=r"((r)[0]), "=r"((r)[1]), "=r"((r)[2]), "=r"((r)[3]) : "r"(addr))
#define MBARRIER_INIT(mb, c) \
    asm volatile("mbarrier.init.shared.b64 [%0], %1;" :: "r"((uint32_t)(mb)), "r"((uint32_t)(c)) : "memory")
#define MBARRIER_EXPECT_TX(mb, tx) \
    asm volatile("mbarrier.arrive.expect_tx.shared.b64 _, [%0], %1;" :: "r"((uint32_t)(mb)), "r"((uint32_t)(tx)) : "memory")
#define CPBULK(dst, src, bytes, mb) \
    asm volatile("cp.async.bulk.shared::cta.global.mbarrier::complete_tx::bytes [%0], [%1], %2, [%3];" \
                 :: "r"((uint32_t)(dst)), "l"(src), "r"((uint32_t)(bytes)), "r"((uint32_t)(mb)) : "memory")
#define MBARRIER_WAIT_PARITY(mb, par) do { \
    uint32_t _m = (uint32_t)(mb); uint32_t _p = (uint32_t)(par); uint32_t _d; \
    asm volatile("{\n\t.reg .pred p;\n\t" \
        "mbarrier.try_wait.parity.acquire.cta.shared::cta.b64 p, [%1], %2;\n\t" \
        "selp.b32 %0, 1, 0, p;\n\t}" : "=r"(_d) : "r"(_m), "r"(_p) : "memory"); \
    if (!_d) { \
        asm volatile("{\n\t.reg .pred P1;\n\tWL_%=:\n\t" \
            "mbarrier.try_wait.parity.acquire.cta.shared::cta.b64 P1, [%0], %1, 0x989680;\n\t" \
            "@P1 bra.uni WD_%=;\n\tbra.uni WL_%=;\n\tWD_%=:\n\t}" \
            :: "r"(_m), "r"(_p) : "memory"); \
    } } while (0)

__device__ __forceinline__ void mma16816(float* c, const uint32_t* a, uint32_t b0, uint32_t b1) {
    asm volatile(
        "mma.sync.aligned.m16n8k16.row.col.f32.bf16.bf16.f32 "
        "{%0,%1,%2,%3},{%4,%5,%6,%7},{%8,%9},{%0,%1,%2,%3};"
        : "+f"(c[0]), "+f"(c[1]), "+f"(c[2]), "+f"(c[3])
        : "r"(a[0]), "r"(a[1]), "r"(a[2]), "r"(a[3]), "r"(b0), "r"(b1));
}

// ---------------- fused conv + e2: one warp per code ----------------
// Converts emb row to bf16 XOR-swizzled layout AND computes e2 in one pass.
__global__ void conv_e2_kernel(const float* __restrict__ e) {
    if (blockIdx.x == 0 && threadIdx.x == 0) g_accum = 0.0;   // replay-safe reset
    int code = blockIdx.x * 8 + (threadIdx.x >> 5);
    int lane = threadIdx.x & 31;
    const float4* p = (const float4*)(e + (size_t)code * DIM);
    float s = 0.f;
#pragma unroll
    for (int j = 0; j < 2; j++) {
        int u8 = lane + 32 * j;                 // float4 index within row, 0..63
        float4 f = p[u8];
        s = __fmaf_rn(f.x, f.x, s); s = __fmaf_rn(f.y, f.y, s);
        s = __fmaf_rn(f.z, f.z, s); s = __fmaf_rn(f.w, f.w, s);
        __nv_bfloat162 h0 = __floats2bfloat162_rn(f.x, f.y);
        __nv_bfloat162 h1 = __floats2bfloat162_rn(f.z, f.w);
        uint2 u; u.x = *(uint32_t*)&h0; u.y = *(uint32_t*)&h1;
        int phys = (u8 >> 1) ^ (code & 7);
        *(uint2*)((char*)g_eb + (size_t)code * 512 + phys * 16 + (u8 & 1) * 8) = u;
    }
#pragma unroll
    for (int o = 16; o; o >>= 1) s += __shfl_down_sync(0xffffffffu, s, o);
    if (lane == 0) { g_e2[code] = s; atomicMax(&g_e2max_bits, __float_as_int(s)); }
}

// ---------------- phase 1: mma.sync bf16 GEMM + dot-margin pruning ----------
// 128 threads (4 warps), 64 rows/CTA, 64-code emb tiles, 2 CTAs/SM.
__global__ __launch_bounds__(128, 2) void vq_mma(const float* __restrict__ z_e) {
    extern __shared__ char sm[];
    int*   scnt = (int*)(sm + 3 * EB);
    float* x2s  = (float*)(sm + 3 * EB + 256);
    const uint32_t sb = smem_u32(sm);
    const uint32_t bar0 = sb + 3 * EB + 512, bar1 = bar0 + 8;
    const int tid = threadIdx.x, lane = tid & 31, w = tid >> 5;
    const int n0 = blockIdx.x * MT;

    if (tid < MT) scnt[tid] = 0;
    if (tid == 0) { MBARRIER_INIT(bar0, 1); MBARRIER_INIT(bar1, 1); }
    __syncthreads();
    if (tid == 0) {
        MBARRIER_EXPECT_TX(bar0, EB);
        CPBULK(sb + EB, (const char*)g_eb, EB, bar0);
        MBARRIER_EXPECT_TX(bar1, EB);
        CPBULK(sb + 2 * EB, (const char*)g_eb + EB, EB, bar1);
    }

    // z tile: load fp32, convert to bf16, store swizzled (overlaps bulk loads)
    {
        const float4* gz = (const float4*)(z_e + (size_t)n0 * DIM);
#pragma unroll
        for (int t = 0; t < 32; t++) {
            int i = tid + t * 128;              // 4096 float4 total
            int row = i >> 6, u8 = i & 63;
            float4 f = gz[i];
            __nv_bfloat162 h0 = __floats2bfloat162_rn(f.x, f.y);
            __nv_bfloat162 h1 = __floats2bfloat162_rn(f.z, f.w);
            uint2 u; u.x = *(uint32_t*)&h0; u.y = *(uint32_t*)&h1;
            int phys = (u8 >> 1) ^ (row & 7);
            *(uint2*)(sm + row * 512 + phys * 16 + (u8 & 1) * 8) = u;
        }
    }
    __syncthreads();

    // x2 per row from bf16 tile (margin use only)
    if (tid < MT) {
        const __nv_bfloat162* zr = (const __nv_bfloat162*)(sm + tid * 512);
        float s = 0.f;
#pragma unroll 8
        for (int d = 0; d < 128; d++) {
            float2 f = __bfloat1622float2(zr[d]);
            s = __fmaf_rn(f.x, f.x, s);
            s = __fmaf_rn(f.y, f.y, s);
        }
        x2s[tid] = s;
    }
    __syncthreads();

    // persistent A fragments: this warp's 16 rows x full D=256
    const int lm = lane >> 3, lr = lane & 7;
    const int ca = lm >> 1;
    uint32_t a[16][4];
    {
        uint32_t aRow = sb + (uint32_t)(w * 16 + lr + (lm & 1) * 8) * 512;
#pragma unroll
        for (int ks = 0; ks < 16; ks++)
            LDSM4(a[ks], aRow + (uint32_t)(((2 * ks + ca) ^ lr) << 4));
    }

    // pruning state: rows (w*16 + g) and (+8), g = lane>>2
    const int g = lane >> 2, tq = lane & 3;
    const int rowloc0 = w * 16 + g;
    const float e2max = __int_as_float(g_e2max_bits);
    float margd[2], rmax[2], thr[2];
#pragma unroll
    for (int rs = 0; rs < 2; rs++) {
        margd[rs] = 0.0079f * sqrtf(x2s[rowloc0 + rs * 8] * e2max) + 1.0e-4f;
        rmax[rs] = -CUDART_INF_F;
        thr[rs]  = -CUDART_INF_F;
    }
    const int cb = lm & 1;
    const uint32_t rB = (uint32_t)(((lm >> 1) & 1) * 8 + lr) * 512;

    for (int t = 0; t < NT2; t++) {
        MBARRIER_WAIT_PARITY(t & 1 ? bar1 : bar0, (t >> 1) & 1);
        const uint32_t eB = sb + EB + (uint32_t)(t & 1) * EB;

        float C[8][4];
#pragma unroll
        for (int i = 0; i < 8; i++)
#pragma unroll
            for (int j = 0; j < 4; j++) C[i][j] = 0.f;

        uint32_t ba[4];
#pragma unroll
        for (int p = 0; p < 4; p++)
            ba[p] = eB + (uint32_t)(p * 16) * 512 + rB;

        uint32_t b[2][16];
#pragma unroll
        for (int p = 0; p < 4; p++)
            LDSM4(&b[0][p * 4], ba[p] + (uint32_t)((cb ^ lr) << 4));
#pragma unroll
        for (int ks = 0; ks < 16; ks++) {
            const int cur = ks & 1, nxt = cur ^ 1;
            if (ks < 15) {
                uint32_t off = (uint32_t)(((2 * (ks + 1) + cb) ^ lr) << 4);
#pragma unroll
                for (int p = 0; p < 4; p++) LDSM4(&b[nxt][p * 4], ba[p] + off);
            }
#pragma unroll
            for (int q = 0; q < 2; q++) {
                mma16816(C[q * 4 + 0], a[ks], b[cur][q * 8 + 0], b[cur][q * 8 + 1]);
                mma16816(C[q * 4 + 1], a[ks], b[cur][q * 8 + 2], b[cur][q * 8 + 3]);
                mma16816(C[q * 4 + 2], a[ks], b[cur][q * 8 + 4], b[cur][q * 8 + 5]);
                mma16816(C[q * 4 + 3], a[ks], b[cur][q * 8 + 6], b[cur][q * 8 + 7]);
            }
        }

        // epilogue: capture k (and its dot) iff dot >= rowmax - margd
#pragma unroll
        for (int q = 0; q < 2; q++) {
            int kc = t * TN + q * 32 + 2 * tq;
#pragma unroll
            for (int nt = 0; nt < 4; nt++) {
#pragma unroll
                for (int r = 0; r < 4; r++) {
                    float d = C[q * 4 + nt][r];
                    int rs = r >> 1;
                    if (d >= thr[rs]) {
                        int rl = rowloc0 + rs * 8;
                        int idx = atomicAdd(&scnt[rl], 1);
                        if (idx < CAP) {
                            g_cand[(size_t)(n0 + rl) * CAP + idx] = kc + nt * 8 + (r & 1);
                            g_cdot[(size_t)(n0 + rl) * CAP + idx] = d;
                        }
                        if (d > rmax[rs]) { rmax[rs] = d; thr[rs] = d - margd[rs]; }
                    }
                }
            }
        }
        // share running max across the 4 owner lanes
#pragma unroll
        for (int rs = 0; rs < 2; rs++) {
            float m = rmax[rs];
            m = fmaxf(m, __shfl_xor_sync(0xffffffffu, m, 1));
            m = fmaxf(m, __shfl_xor_sync(0xffffffffu, m, 2));
            rmax[rs] = m;
            thr[rs] = m - margd[rs];
        }

        __syncthreads();   // all warps done with buffer t&1
        if (tid == 0 && t + 2 < NT2) {
            uint32_t mb = (t & 1) ? bar1 : bar0;
            MBARRIER_EXPECT_TX(mb, EB);
            CPBULK(sb + EB + (uint32_t)(t & 1) * EB,
                   (const char*)g_eb + (size_t)(t + 2) * EB, EB, mb);
        }
    }

    // final thresholds + counts
    if (tq == 0) {
        g_thr[n0 + rowloc0]     = rmax[0] - margd[0];
        g_thr[n0 + rowloc0 + 8] = rmax[1] - margd[1];
    }
    __syncthreads();
    if (tid < MT) {
        int c = scnt[tid];
        g_cnt[n0 + tid] = c < CAP ? c : CAP;
        g_over[n0 + tid] = (c > CAP) ? 1 : 0;
    }
}

// ---------------- phase 2: exact fp32 rescoring (final-threshold filtered) --
__global__ void vq_exact(const float* __restrict__ z_e, const float* __restrict__ emb,
                         float* __restrict__ out) {
    __shared__ float zrow[8][DIM];
    int wid = threadIdx.x >> 5, lane = threadIdx.x & 31;
    int row = blockIdx.x * 8 + wid;
    {
        const float4* gz = (const float4*)(z_e + (size_t)row * DIM);
#pragma unroll
        for (int i = 0; i < 2; i++) {
            float4 v = gz[lane + 32 * i];
            *(float4*)&zrow[wid][4 * (lane + 32 * i)] = v;
        }
    }
    __syncwarp();
    const float* zr = zrow[wid];
    float x2 = 0.f;
    for (int d = 0; d < DIM; d++) x2 = __fmaf_rn(zr[d], zr[d], x2);

    float bt = CUDART_INF_F;
    int bk = 0x7fffffff;
    int cnt = g_cnt[row];
    bool over = g_over[row] != 0;
    float thrf = g_thr[row];
    int total = over ? KCODES : cnt;
    for (int c = lane; c < total; c += 32) {
        int k;
        if (over) k = c;
        else {
            if (g_cdot[(size_t)row * CAP + c] < thrf) continue;   // prefix junk
            k = g_cand[(size_t)row * CAP + c];
        }
        const float4* er = (const float4*)(emb + (size_t)k * DIM);
        float dot = 0.f;
#pragma unroll 8
        for (int q = 0; q < DIM / 4; q++) {
            float4 e4 = er[q];
            dot = __fmaf_rn(zr[4 * q + 0], e4.x, dot);
            dot = __fmaf_rn(zr[4 * q + 1], e4.y, dot);
            dot = __fmaf_rn(zr[4 * q + 2], e4.z, dot);
            dot = __fmaf_rn(zr[4 * q + 3], e4.w, dot);
        }
        float S = __fadd_rn(x2, g_e2[k]);
        float tt = __fadd_rn(S, -2.0f * dot);
        if (tt < bt || (tt == bt && k < bk)) { bt = tt; bk = k; }
    }
#pragma unroll
    for (int o = 16; o; o >>= 1) {
        float to = __shfl_down_sync(0xffffffffu, bt, o);
        int ko = __shfl_down_sync(0xffffffffu, bk, o);
        if (to < bt || (to == bt && ko < bk)) { bt = to; bk = ko; }
    }
    bk = __shfl_sync(0xffffffffu, bk, 0);

    // fused gather: z_q_st + loss partial + code output
    const float4* er = (const float4*)(emb + (size_t)bk * DIM);
    float4* po = (float4*)(out + (size_t)row * DIM);
    float sq = 0.f;
#pragma unroll
    for (int j = 0; j < 2; j++) {
        int q = lane + 32 * j;
        float4 e4 = er[q];
        const float* zp = &zrow[wid][4 * q];
        float4 o4;
        float d0 = __fsub_rn(e4.x, zp[0]); o4.x = __fadd_rn(zp[0], d0); sq = __fmaf_rn(d0, d0, sq);
        float d1 = __fsub_rn(e4.y, zp[1]); o4.y = __fadd_rn(zp[1], d1); sq = __fmaf_rn(d1, d1, sq);
        float d2 = __fsub_rn(e4.z, zp[2]); o4.z = __fadd_rn(zp[2], d2); sq = __fmaf_rn(d2, d2, sq);
        float d3 = __fsub_rn(e4.w, zp[3]); o4.w = __fadd_rn(zp[3], d3); sq = __fmaf_rn(d3, d3, sq);
        po[q] = o4;
    }
#pragma unroll
    for (int o = 16; o; o >>= 1) sq += __shfl_down_sync(0xffffffffu, sq, o);
    if (lane == 0) {
        atomicAdd(&g_accum, (double)sq);
        out[(size_t)NROWS * DIM + 1 + row] = (float)bk;
    }
}

__global__ void vq_loss(float* __restrict__ out) {
    float m = (float)(g_accum / (double)((size_t)NROWS * DIM));
    out[(size_t)NROWS * DIM] = __fadd_rn(m, 0.25f * m);
}

// ---------------------------------------------------------------------------
extern "C" void kernel_launch(void* const* d_in, const int* in_sizes, int n_in,
                              void* d_out, int out_size) {
    const float* z_e = (const float*)d_in[0];
    const float* emb = (const float*)d_in[1];
    if (n_in >= 2 && in_sizes[0] == KCODES * DIM && in_sizes[1] == NROWS * DIM) {
        const float* t = z_e; z_e = emb; emb = t;
    }
    float* out = (float*)d_out;

    cudaFuncSetAttribute(vq_mma, cudaFuncAttributeMaxDynamicSharedMemorySize, SMEM_TOT);

    conv_e2_kernel<<<KCODES / 8, 256>>>(emb);
    vq_mma<<<NROWS / MT, 128, SMEM_TOT>>>(z_e);
    vq_exact<<<NROWS / 8, 256>>>(z_e, emb, out);
    vq_loss<<<1, 1>>>(out);
}